// round 17
// baseline (speedup 1.0000x reference)
#include <cuda_runtime.h>
#include <cstdint>

// S=64, B=128, D=10000 fixed by the reference.
#define D_DIM   10000
#define D4      2500
#define S_DIM   64
#define B_DIM   128
#define THREADS 512
#define NWARPS  16
#define NCH     39            // 39 chunks x 64 quads = 2496; tail = 4 quads (lane<4)
#define CHB     1024          // bytes per sample per chunk
#define TY_BYTES  80000
#define BUF_BYTES (NWARPS * 2 * 4 * CHB)       // 131072
#define MBAR_OFF  (TY_BYTES + BUF_BYTES)       // 211072
#define SMEM_BYTES (MBAR_OFF + NWARPS * 2 * 8) // 211328

#define L2E 1.4426950408889634f

__device__ float    g_partial[B_DIM];
__device__ unsigned g_ticket;      // zero-init; reset by last CTA each launch

__device__ __forceinline__ float ex2f(float x) {
    float r;
    asm("ex2.approx.ftz.f32 %0, %1;" : "=f"(r) : "f"(x));
    return r;
}

__device__ __forceinline__ void mbar_init(uint32_t mbar, uint32_t cnt) {
    asm volatile("mbarrier.init.shared.b64 [%0], %1;" :: "r"(mbar), "r"(cnt) : "memory");
}
__device__ __forceinline__ void mbar_expect_tx(uint32_t mbar, uint32_t tx) {
    asm volatile("mbarrier.arrive.expect_tx.shared.b64 _, [%0], %1;"
                 :: "r"(mbar), "r"(tx) : "memory");
}
__device__ __forceinline__ void mbar_wait(uint32_t mbar, uint32_t parity) {
    asm volatile(
        "{\n\t"
        ".reg .pred P;\n\t"
        "WL_%=:\n\t"
        "mbarrier.try_wait.parity.acquire.cta.shared::cta.b64 P, [%0], %1, 0x989680;\n\t"
        "@P bra.uni WD_%=;\n\t"
        "bra.uni WL_%=;\n\t"
        "WD_%=:\n\t"
        "}"
        :: "r"(mbar), "r"(parity) : "memory");
}
__device__ __forceinline__ void tma_bulk_1d(uint32_t dst_smem, const void* src,
                                            uint32_t bytes, uint32_t mbar) {
    asm volatile(
        "cp.async.bulk.shared::cta.global.mbarrier::complete_tx::bytes "
        "[%0], [%1], %2, [%3];"
        :: "r"(dst_smem), "l"(src), "r"(bytes), "r"(mbar) : "memory");
}

// consume one quad (noise n, theta*log2e t, y yv) into one sample's accumulators
__device__ __forceinline__ void consume1(const float4& n, const float4& t,
                                         const float4& yv,
                                         float& sq, float& sq2, float& sqy)
{
    float qx = ex2f(fmaf(n.x, L2E, t.x));
    float qy = ex2f(fmaf(n.y, L2E, t.y));
    float qz = ex2f(fmaf(n.z, L2E, t.z));
    float qw = ex2f(fmaf(n.w, L2E, t.w));
    sq  += (qx + qy) + (qz + qw);
    sq2 = fmaf(qx, qx, sq2);   sq2 = fmaf(qy, qy, sq2);
    sq2 = fmaf(qz, qz, sq2);   sq2 = fmaf(qw, qw, sq2);
    sqy = fmaf(qx, yv.x, sqy); sqy = fmaf(qy, yv.y, sqy);
    sqy = fmaf(qz, yv.z, sqy); sqy = fmaf(qw, yv.w, sqy);
}

__global__ __launch_bounds__(THREADS, 1)
void pl_fused(const float* __restrict__ theta,
              const float* __restrict__ y,
              const float* __restrict__ noise,
              float* __restrict__ out)
{
    extern __shared__ float sm[];
    char* smc = (char*)sm;
    float* __restrict__ sth = sm;              // [0, 10000): theta*log2e
    float* __restrict__ syy = sm + D_DIM;      // [10000, 20000): y
    __shared__ float fin[NWARPS];
    __shared__ int   is_last;

    uint32_t smem_base;
    asm("{ .reg .u64 t; cvta.to.shared.u64 t, %1; cvt.u32.u64 %0, t; }"
        : "=r"(smem_base) : "l"(sm));

    const int b    = blockIdx.x;
    const int tid  = threadIdx.x;
    const int lane = tid & 31;
    const int warp = tid >> 5;

    // ---- per-warp mbarriers + buffer addresses ----
    const uint32_t mb0 = smem_base + MBAR_OFF + warp * 16;
    const uint32_t mb1 = mb0 + 8;
    if (lane == 0) { mbar_init(mb0, 1); mbar_init(mb1, 1); }
    __syncwarp();
    asm volatile("fence.proxy.async.shared::cta;" ::: "memory");

    const uint32_t bufw_s = smem_base + TY_BYTES + warp * (2 * 4 * CHB);
    const char*    bufw_g = smc + TY_BYTES + warp * (2 * 4 * CHB);

    // global row pointers: warp owns samples 4*warp .. 4*warp+3
    const size_t rowbytes = (size_t)B_DIM * D_DIM * sizeof(float);
    const char* nzr = (const char*)noise +
        ((size_t)(4 * warp) * B_DIM + b) * D_DIM * sizeof(float);
    const char* nz[4] = { nzr, nzr + rowbytes, nzr + 2 * rowbytes, nzr + 3 * rowbytes };

    // ---- prime chunks 0 and 1 (DRAM stream starts before theta/y staging) ----
    if (lane == 0) {
        #pragma unroll
        for (int k = 0; k < 2; k++) {
            const uint32_t mb = k ? mb1 : mb0;
            mbar_expect_tx(mb, 4 * CHB);
            #pragma unroll
            for (int j = 0; j < 4; j++)
                tma_bulk_1d(bufw_s + k * 4 * CHB + j * CHB,
                            nz[j] + (size_t)k * CHB, CHB, mb);
        }
    }

    // ---- stage theta*log2e, y into shared; per-thread partial Sigma(y^2) ----
    float sy2p = 0.0f;
    {
        const float4* __restrict__ th4 = (const float4*)(theta + (size_t)b * D_DIM);
        const float4* __restrict__ yy4 = (const float4*)(y     + (size_t)b * D_DIM);
        float4* s_t = (float4*)sth;
        float4* s_y = (float4*)syy;
        for (int i = tid; i < D4; i += THREADS) {
            float4 t = __ldg(th4 + i);
            float4 v = __ldg(yy4 + i);
            sy2p = fmaf(v.x, v.x, sy2p);
            sy2p = fmaf(v.y, v.y, sy2p);
            sy2p = fmaf(v.z, v.z, sy2p);
            sy2p = fmaf(v.w, v.w, sy2p);
            t.x *= L2E; t.y *= L2E; t.z *= L2E; t.w *= L2E;
            s_t[i] = t;
            s_y[i] = v;
        }
    }
    __syncthreads();   // theta/y visible to all warps

    const float4* __restrict__ st4 = (const float4*)sth;
    const float4* __restrict__ sy4 = (const float4*)syy;

    float q0 = 0.f, q0s = 0.f, q0y = 0.f;
    float q1 = 0.f, q1s = 0.f, q1y = 0.f;
    float q2 = 0.f, q2s = 0.f, q2y = 0.f;
    float q3 = 0.f, q3s = 0.f, q3y = 0.f;

    // ---- chunk loop: wait own mbar, consume 2 quads/lane/sample, reissue c+2 ----
    #pragma unroll 1
    for (int c = 0; c < NCH; c++) {
        const int k  = c & 1;
        const int ph = (c >> 1) & 1;
        const uint32_t mb = k ? mb1 : mb0;
        mbar_wait(mb, ph);

        const float4* buf = (const float4*)(bufw_g + k * 4 * CHB);
        const int f = c * 64 + 2 * lane;
        const float4 t0 = st4[f],     y0 = sy4[f];
        const float4 t1 = st4[f + 1], y1 = sy4[f + 1];
        const int li = 2 * lane;
        consume1(buf[li],           t0, y0, q0, q0s, q0y);
        consume1(buf[li + 1],       t1, y1, q0, q0s, q0y);
        consume1(buf[64 + li],      t0, y0, q1, q1s, q1y);
        consume1(buf[64 + li + 1],  t1, y1, q1, q1s, q1y);
        consume1(buf[128 + li],     t0, y0, q2, q2s, q2y);
        consume1(buf[128 + li + 1], t1, y1, q2, q2s, q2y);
        consume1(buf[192 + li],     t0, y0, q3, q3s, q3y);
        consume1(buf[192 + li + 1], t1, y1, q3, q3s, q3y);

        if (c + 2 < NCH && lane == 0) {
            mbar_expect_tx(mb, 4 * CHB);
            #pragma unroll
            for (int j = 0; j < 4; j++)
                tma_bulk_1d(bufw_s + k * 4 * CHB + j * CHB,
                            nz[j] + (size_t)(c + 2) * CHB, CHB, mb);
        }
    }

    // ---- tail quads 2496..2499 via direct LDG (lane<4) ----
    if (lane < 4) {
        const size_t off = (size_t)(2496 + lane) * 16;
        const int idx = 2496 + lane;
        float4 t = st4[idx], yv = sy4[idx];
        consume1(*(const float4*)(nz[0] + off), t, yv, q0, q0s, q0y);
        consume1(*(const float4*)(nz[1] + off), t, yv, q1, q1s, q1y);
        consume1(*(const float4*)(nz[2] + off), t, yv, q2, q2s, q2y);
        consume1(*(const float4*)(nz[3] + off), t, yv, q3, q3s, q3y);
    }

    // ---- warp-local reductions: four samples + deferred Sigma(y^2) ----
    #pragma unroll
    for (int o = 16; o; o >>= 1) {
        q0  += __shfl_xor_sync(0xffffffffu, q0,  o);
        q0s += __shfl_xor_sync(0xffffffffu, q0s, o);
        q0y += __shfl_xor_sync(0xffffffffu, q0y, o);
        q1  += __shfl_xor_sync(0xffffffffu, q1,  o);
        q1s += __shfl_xor_sync(0xffffffffu, q1s, o);
        q1y += __shfl_xor_sync(0xffffffffu, q1y, o);
        q2  += __shfl_xor_sync(0xffffffffu, q2,  o);
        q2s += __shfl_xor_sync(0xffffffffu, q2s, o);
        q2y += __shfl_xor_sync(0xffffffffu, q2y, o);
        q3  += __shfl_xor_sync(0xffffffffu, q3,  o);
        q3s += __shfl_xor_sync(0xffffffffu, q3s, o);
        q3y += __shfl_xor_sync(0xffffffffu, q3y, o);
        sy2p += __shfl_xor_sync(0xffffffffu, sy2p, o);
    }
    const float i0 = __frcp_rn(q0);
    const float i1 = __frcp_rn(q1);
    const float i2 = __frcp_rn(q2);
    const float i3 = __frcp_rn(q3);
    float acc = fmaf(i0 * i0, q0s, -2.0f * i0 * q0y)
              + fmaf(i1 * i1, q1s, -2.0f * i1 * q1y)
              + fmaf(i2 * i2, q2s, -2.0f * i2 * q2y)
              + fmaf(i3 * i3, q3s, -2.0f * i3 * q3y)
              + (float)S_DIM * sy2p;

    // ---- block combine (single barrier) + fused grid reduction ----
    if (lane == 0) fin[warp] = acc;
    __syncthreads();
    if (tid == 0) {
        float tot = fin[0];
        #pragma unroll
        for (int w = 1; w < NWARPS; w++) tot += fin[w];
        g_partial[b] = tot;
        __threadfence();
        unsigned t = atomicAdd(&g_ticket, 1u);
        is_last = (t == B_DIM - 1) ? 1 : 0;
    }
    __syncthreads();

    if (is_last) {
        if (tid < B_DIM) {                     // warps 0..3
            float v = __ldcg(&g_partial[tid]);
            #pragma unroll
            for (int o = 16; o; o >>= 1) v += __shfl_xor_sync(0xffffffffu, v, o);
            if (lane == 0) fin[warp] = v;
        }
        __syncthreads();
        if (tid == 0) {
            float tot = fin[0] + fin[1] + fin[2] + fin[3];
            out[0] = tot * (1.0f / ((float)S_DIM * (float)B_DIM * (float)D_DIM));
            g_ticket = 0u;                      // reset for next graph replay
        }
    }
}

extern "C" void kernel_launch(void* const* d_in, const int* in_sizes, int n_in,
                              void* d_out, int out_size)
{
    const float* theta = (const float*)d_in[0];  // [B, D]
    const float* y     = (const float*)d_in[1];  // [B, D]
    const float* noise = (const float*)d_in[2];  // [S, B, D]
    float* out = (float*)d_out;

    cudaFuncSetAttribute(pl_fused,
                         cudaFuncAttributeMaxDynamicSharedMemorySize,
                         SMEM_BYTES);
    pl_fused<<<B_DIM, THREADS, SMEM_BYTES>>>(theta, y, noise, out);
}